// round 1
// baseline (speedup 1.0000x reference)
#include <cuda_runtime.h>

#define Bn   8
#define Cc   256
#define HWn  4096
#define GRP  8
#define CPG  32   // channels per group

// ---------------- scratch (static device globals; no runtime allocation) ----
__device__ float g_xn[(size_t)Bn * HWn * Cc];   // groupnorm output, token-major [b][p][c]
__device__ float g_q [(size_t)Bn * HWn * Cc];   // [b][p][c]
__device__ float g_k [(size_t)Bn * HWn * Cc];   // [b][p][c]
__device__ float g_v [(size_t)Bn * HWn * Cc];   // [b][p][c]
__device__ float g_ao[(size_t)Bn * HWn * Cc];   // attention output [b][p][c]
__device__ float g_sc[(size_t)Bn * HWn * HWn];  // scores/attn [b][n][m]  (536 MB)

// ---------------- GroupNorm: x[b][c][p] -> g_xn[b][p][c] --------------------
__global__ __launch_bounds__(512) void gn_kernel(const float* __restrict__ x,
                                                 const float* __restrict__ w,
                                                 const float* __restrict__ bv) {
    int bg = blockIdx.x;
    int b = bg >> 3, g = bg & 7;
    const float* xb = x + ((size_t)b * Cc + (size_t)g * CPG) * HWn; // group is contiguous
    const int NEL = CPG * HWn; // 131072

    float s = 0.f, ss = 0.f;
    for (int i = threadIdx.x; i < NEL; i += blockDim.x) {
        float v = xb[i];
        s += v; ss += v * v;
    }
    __shared__ float rs[32], rss[32];
    #pragma unroll
    for (int o = 16; o; o >>= 1) {
        s  += __shfl_down_sync(0xffffffffu, s, o);
        ss += __shfl_down_sync(0xffffffffu, ss, o);
    }
    int lane = threadIdx.x & 31, wid = threadIdx.x >> 5;
    if (lane == 0) { rs[wid] = s; rss[wid] = ss; }
    __syncthreads();
    if (wid == 0) {
        s  = (lane < 16) ? rs[lane]  : 0.f;
        ss = (lane < 16) ? rss[lane] : 0.f;
        #pragma unroll
        for (int o = 16; o; o >>= 1) {
            s  += __shfl_down_sync(0xffffffffu, s, o);
            ss += __shfl_down_sync(0xffffffffu, ss, o);
        }
        if (lane == 0) { rs[0] = s; rss[0] = ss; }
    }
    __syncthreads();
    float mean = rs[0] / (float)NEL;
    float var  = rss[0] / (float)NEL - mean * mean;
    float rstd = rsqrtf(var + 1e-5f);

    float* out = g_xn + (size_t)b * HWn * Cc + (size_t)g * CPG;
    for (int i = threadIdx.x; i < NEL; i += blockDim.x) {
        int c = i & 31;       // channel within group (fast -> coalesced writes)
        int p = i >> 5;       // pixel
        float v = xb[(size_t)c * HWn + p];   // L2-resident after pass 1
        out[(size_t)p * Cc + c] = (v - mean) * rstd * w[g * CPG + c] + bv[g * CPG + c];
    }
}

// ---------------- QKV: q/k/v[b][p][o] = sum_c xn[b][p][c] * W[o][c] + bias --
__global__ __launch_bounds__(256) void qkv_kernel(const float* __restrict__ W,
                                                  const float* __restrict__ bias) {
    int b = blockIdx.z;
    const float* A = g_xn + (size_t)b * HWn * Cc;
    int pm = blockIdx.y * 64;   // token tile
    int on = blockIdx.x * 64;   // output-channel tile (0..767)
    __shared__ float As[64][17];
    __shared__ float Bs[64][17];
    int tx = threadIdx.x, ty = threadIdx.y;
    int t = ty * 16 + tx;
    float acc[4][4] = {};

    for (int kb = 0; kb < Cc; kb += 16) {
        #pragma unroll
        for (int i = 0; i < 4; i++) {
            int lin = t + 256 * i;
            int r = lin >> 4, kk = lin & 15;
            As[r][kk] = A[(size_t)(pm + r) * Cc + kb + kk];
            Bs[r][kk] = W[(size_t)(on + r) * Cc + kb + kk];
        }
        __syncthreads();
        #pragma unroll
        for (int kk = 0; kk < 16; kk++) {
            float a0[4], b0[4];
            #pragma unroll
            for (int i = 0; i < 4; i++) a0[i] = As[ty * 4 + i][kk];
            #pragma unroll
            for (int j = 0; j < 4; j++) b0[j] = Bs[tx * 4 + j][kk];
            #pragma unroll
            for (int i = 0; i < 4; i++)
                #pragma unroll
                for (int j = 0; j < 4; j++)
                    acc[i][j] += a0[i] * b0[j];
        }
        __syncthreads();
    }

    int obase = on + tx * 4;
    float* dst = (obase < 256) ? g_q : (obase < 512) ? g_k : g_v;
    int oo = obase & 255;
    float4 b4 = *(const float4*)&bias[obase];
    #pragma unroll
    for (int i = 0; i < 4; i++) {
        int p = pm + ty * 4 + i;
        float4 v4;
        v4.x = acc[i][0] + b4.x; v4.y = acc[i][1] + b4.y;
        v4.z = acc[i][2] + b4.z; v4.w = acc[i][3] + b4.w;
        *(float4*)&dst[(size_t)b * HWn * Cc + (size_t)p * Cc + oo] = v4;
    }
}

// ---------------- scores[b][n][m] = (q[n]·k[m]) / 16 ------------------------
__global__ __launch_bounds__(256) void scores_kernel() {
    int b = blockIdx.z;
    const float* Q = g_q + (size_t)b * HWn * Cc;
    const float* K = g_k + (size_t)b * HWn * Cc;
    int nm = blockIdx.y * 64;   // n tile
    int mn = blockIdx.x * 64;   // m tile
    __shared__ float As[64][17];
    __shared__ float Bs[64][17];
    int tx = threadIdx.x, ty = threadIdx.y;
    int t = ty * 16 + tx;
    float acc[4][4] = {};

    for (int kb = 0; kb < Cc; kb += 16) {
        #pragma unroll
        for (int i = 0; i < 4; i++) {
            int lin = t + 256 * i;
            int r = lin >> 4, kk = lin & 15;
            As[r][kk] = Q[(size_t)(nm + r) * Cc + kb + kk];
            Bs[r][kk] = K[(size_t)(mn + r) * Cc + kb + kk];
        }
        __syncthreads();
        #pragma unroll
        for (int kk = 0; kk < 16; kk++) {
            float a0[4], b0[4];
            #pragma unroll
            for (int i = 0; i < 4; i++) a0[i] = As[ty * 4 + i][kk];
            #pragma unroll
            for (int j = 0; j < 4; j++) b0[j] = Bs[tx * 4 + j][kk];
            #pragma unroll
            for (int i = 0; i < 4; i++)
                #pragma unroll
                for (int j = 0; j < 4; j++)
                    acc[i][j] += a0[i] * b0[j];
        }
        __syncthreads();
    }

    const float scale = 0.0625f; // 1/sqrt(256)
    int mbase = mn + tx * 4;
    #pragma unroll
    for (int i = 0; i < 4; i++) {
        int n = nm + ty * 4 + i;
        float4 v4;
        v4.x = acc[i][0] * scale; v4.y = acc[i][1] * scale;
        v4.z = acc[i][2] * scale; v4.w = acc[i][3] * scale;
        *(float4*)&g_sc[((size_t)b * HWn + n) * HWn + mbase] = v4;
    }
}

// ---------------- row softmax over m (4096) ----------------------------------
__global__ __launch_bounds__(256) void softmax_kernel() {
    size_t row = blockIdx.x;
    float* S = g_sc + row * HWn;
    float v[16];
    float mx = -1e30f;
    #pragma unroll
    for (int i = 0; i < 16; i++) {
        v[i] = S[threadIdx.x + 256 * i];
        mx = fmaxf(mx, v[i]);
    }
    __shared__ float redm[8], reds[8];
    int lane = threadIdx.x & 31, wid = threadIdx.x >> 5;
    #pragma unroll
    for (int o = 16; o; o >>= 1) mx = fmaxf(mx, __shfl_xor_sync(0xffffffffu, mx, o));
    if (lane == 0) redm[wid] = mx;
    __syncthreads();
    mx = redm[0];
    #pragma unroll
    for (int i = 1; i < 8; i++) mx = fmaxf(mx, redm[i]);

    float sum = 0.f;
    #pragma unroll
    for (int i = 0; i < 16; i++) {
        v[i] = __expf(v[i] - mx);
        sum += v[i];
    }
    #pragma unroll
    for (int o = 16; o; o >>= 1) sum += __shfl_xor_sync(0xffffffffu, sum, o);
    if (lane == 0) reds[wid] = sum;
    __syncthreads();
    sum = reds[0];
    #pragma unroll
    for (int i = 1; i < 8; i++) sum += reds[i];

    float inv = 1.0f / sum;
    #pragma unroll
    for (int i = 0; i < 16; i++)
        S[threadIdx.x + 256 * i] = v[i] * inv;
}

// ---------------- PV: ao[b][n][c] = sum_m attn[n][m] * v[b][m][c] -----------
__global__ __launch_bounds__(256) void pv_kernel() {
    int b = blockIdx.z;
    const float* A = g_sc + (size_t)b * HWn * HWn;   // [4096 x 4096], m contiguous
    const float* V = g_v  + (size_t)b * HWn * Cc;    // [4096 x 256],  c contiguous
    int nm = blockIdx.y * 64;  // n tile
    int cn = blockIdx.x * 64;  // c tile
    __shared__ float As[64][17];
    __shared__ float Bs[16][64];
    int tx = threadIdx.x, ty = threadIdx.y;
    int t = ty * 16 + tx;
    float acc[4][4] = {};

    for (int kb = 0; kb < HWn; kb += 16) {
        #pragma unroll
        for (int i = 0; i < 4; i++) {
            int lin = t + 256 * i;
            int r = lin >> 4, kk = lin & 15;
            As[r][kk] = A[(size_t)(nm + r) * HWn + kb + kk];
            int c2 = lin & 63, k2 = lin >> 6;
            Bs[k2][c2] = V[(size_t)(kb + k2) * Cc + cn + c2];
        }
        __syncthreads();
        #pragma unroll
        for (int kk = 0; kk < 16; kk++) {
            float a0[4];
            #pragma unroll
            for (int i = 0; i < 4; i++) a0[i] = As[ty * 4 + i][kk];
            float4 b4 = *(const float4*)&Bs[kk][tx * 4];
            #pragma unroll
            for (int i = 0; i < 4; i++) {
                acc[i][0] += a0[i] * b4.x;
                acc[i][1] += a0[i] * b4.y;
                acc[i][2] += a0[i] * b4.z;
                acc[i][3] += a0[i] * b4.w;
            }
        }
        __syncthreads();
    }

    int cbase = cn + tx * 4;
    #pragma unroll
    for (int i = 0; i < 4; i++) {
        int p = nm + ty * 4 + i;
        float4 v4;
        v4.x = acc[i][0]; v4.y = acc[i][1]; v4.z = acc[i][2]; v4.w = acc[i][3];
        *(float4*)&g_ao[(size_t)b * HWn * Cc + (size_t)p * Cc + cbase] = v4;
    }
}

// ---------------- proj + residual: out[b][o][p] = x + sum_c ao[p][c]W[o][c]+pb
__global__ __launch_bounds__(256) void proj_kernel(const float* __restrict__ x,
                                                   const float* __restrict__ W,
                                                   const float* __restrict__ pb,
                                                   float* __restrict__ out) {
    int b = blockIdx.z;
    const float* AO = g_ao + (size_t)b * HWn * Cc;
    int om = blockIdx.y * 64;  // output-channel tile
    int pn = blockIdx.x * 64;  // token tile
    __shared__ float As[64][17];   // o rows
    __shared__ float Bs[64][17];   // p rows
    int tx = threadIdx.x, ty = threadIdx.y;
    int t = ty * 16 + tx;
    float acc[4][4] = {};

    for (int kb = 0; kb < Cc; kb += 16) {
        #pragma unroll
        for (int i = 0; i < 4; i++) {
            int lin = t + 256 * i;
            int r = lin >> 4, kk = lin & 15;
            As[r][kk] = W[(size_t)(om + r) * Cc + kb + kk];
            Bs[r][kk] = AO[(size_t)(pn + r) * Cc + kb + kk];
        }
        __syncthreads();
        #pragma unroll
        for (int kk = 0; kk < 16; kk++) {
            float a0[4], b0[4];
            #pragma unroll
            for (int i = 0; i < 4; i++) a0[i] = As[ty * 4 + i][kk];
            #pragma unroll
            for (int j = 0; j < 4; j++) b0[j] = Bs[tx * 4 + j][kk];
            #pragma unroll
            for (int i = 0; i < 4; i++)
                #pragma unroll
                for (int j = 0; j < 4; j++)
                    acc[i][j] += a0[i] * b0[j];
        }
        __syncthreads();
    }

    int pbase = pn + tx * 4;
    #pragma unroll
    for (int i = 0; i < 4; i++) {
        int o = om + ty * 4 + i;
        float bo = pb[o];
        size_t off = (size_t)b * Cc * HWn + (size_t)o * HWn + pbase;
        float4 xr = *(const float4*)&x[off];
        float4 v4;
        v4.x = acc[i][0] + bo + xr.x;
        v4.y = acc[i][1] + bo + xr.y;
        v4.z = acc[i][2] + bo + xr.z;
        v4.w = acc[i][3] + bo + xr.w;
        *(float4*)&out[off] = v4;
    }
}

// ---------------- launch -----------------------------------------------------
extern "C" void kernel_launch(void* const* d_in, const int* in_sizes, int n_in,
                              void* d_out, int out_size) {
    const float* x  = (const float*)d_in[0];
    const float* nw = (const float*)d_in[1];
    const float* nb = (const float*)d_in[2];
    const float* qw = (const float*)d_in[3];
    const float* qb = (const float*)d_in[4];
    const float* pw = (const float*)d_in[5];
    const float* pb = (const float*)d_in[6];
    float* out = (float*)d_out;

    dim3 tb(16, 16);
    gn_kernel<<<Bn * GRP, 512>>>(x, nw, nb);
    qkv_kernel<<<dim3(12, 64, 8), tb>>>(qw, qb);
    scores_kernel<<<dim3(64, 64, 8), tb>>>();
    softmax_kernel<<<Bn * HWn, 256>>>();
    pv_kernel<<<dim3(4, 64, 8), tb>>>();
    proj_kernel<<<dim3(64, 4, 8), tb>>>(x, pw, pb, out);
}

// round 2
// speedup vs baseline: 2.7304x; 2.7304x over previous
#include <cuda_runtime.h>
#include <cstdint>

#define Bn   8
#define Cc   256
#define HWn  4096
#define CPG  32
#define PA   20    // smem pitch (floats) for [128 rows][16 k] tiles -> conflict-free
#define PVP  136   // smem pitch (floats) for PV's [16 k][128 c] tile -> conflict-free

// ---------------- scratch -----------------------------------------------------
__device__ float g_xn[(size_t)Bn * HWn * Cc];
__device__ float g_q [(size_t)Bn * HWn * Cc];
__device__ float g_k [(size_t)Bn * HWn * Cc];
__device__ float g_v [(size_t)Bn * HWn * Cc];
__device__ float g_ao[(size_t)Bn * HWn * Cc];
__device__ float g_sc[(size_t)Bn * HWn * HWn];

// ---------------- helpers ------------------------------------------------------
__device__ __forceinline__ float tf32r(float x) {
    uint32_t r;
    asm("cvt.rna.tf32.f32 %0, %1;" : "=r"(r) : "f"(x));
    return __uint_as_float(r);
}
__device__ __forceinline__ float4 tf32r4(float4 v) {
    float4 o; o.x = tf32r(v.x); o.y = tf32r(v.y); o.z = tf32r(v.z); o.w = tf32r(v.w);
    return o;
}
__device__ __forceinline__ void mma8(float c[4], uint32_t a0, uint32_t a1, uint32_t a2,
                                     uint32_t a3, uint32_t b0, uint32_t b1) {
    asm("mma.sync.aligned.m16n8k8.row.col.f32.tf32.tf32.f32 "
        "{%0,%1,%2,%3},{%4,%5,%6,%7},{%8,%9},{%0,%1,%2,%3};"
        : "+f"(c[0]), "+f"(c[1]), "+f"(c[2]), "+f"(c[3])
        : "r"(a0), "r"(a1), "r"(a2), "r"(a3), "r"(b0), "r"(b1));
}
#define U(x) __float_as_uint(x)

// NT mainloop: D[128,128] += A[128,K](row-major, lda) * B[128,K](row-major, ldb)^T
// acc[mt][nt][4]; warp tile 32x64: wm=(wid>>1)*32, wn=(wid&1)*64
__device__ __forceinline__ void gemm_nt(const float* __restrict__ Ag,
                                        const float* __restrict__ Bg,
                                        int K, int lda, int ldb,
                                        float* As, float* Bs,
                                        float acc[2][8][4]) {
    int t = threadIdx.x;
    int r = t >> 1, cc = (t & 1) * 8;
    int wid = t >> 5, lane = t & 31, g = lane >> 2, t4 = lane & 3;
    int wm = (wid >> 1) * 32, wn = (wid & 1) * 64;

    #pragma unroll 1
    for (int kb = 0; kb < K; kb += 16) {
        float4 av0 = *(const float4*)(Ag + (size_t)r * lda + kb + cc);
        float4 av1 = *(const float4*)(Ag + (size_t)r * lda + kb + cc + 4);
        float4 bv0 = *(const float4*)(Bg + (size_t)r * ldb + kb + cc);
        float4 bv1 = *(const float4*)(Bg + (size_t)r * ldb + kb + cc + 4);
        __syncthreads();
        *(float4*)&As[r * PA + cc]     = tf32r4(av0);
        *(float4*)&As[r * PA + cc + 4] = tf32r4(av1);
        *(float4*)&Bs[r * PA + cc]     = tf32r4(bv0);
        *(float4*)&Bs[r * PA + cc + 4] = tf32r4(bv1);
        __syncthreads();
        #pragma unroll
        for (int ks = 0; ks < 16; ks += 8) {
            uint32_t af[2][4];
            #pragma unroll
            for (int mt = 0; mt < 2; mt++) {
                int row = (wm + mt * 16 + g) * PA + ks + t4;
                af[mt][0] = U(As[row]);
                af[mt][1] = U(As[row + 8 * PA]);
                af[mt][2] = U(As[row + 4]);
                af[mt][3] = U(As[row + 8 * PA + 4]);
            }
            uint32_t bf[8][2];
            #pragma unroll
            for (int nt = 0; nt < 8; nt++) {
                int row = (wn + nt * 8 + g) * PA + ks + t4;
                bf[nt][0] = U(Bs[row]);
                bf[nt][1] = U(Bs[row + 4]);
            }
            #pragma unroll
            for (int mt = 0; mt < 2; mt++)
                #pragma unroll
                for (int nt = 0; nt < 8; nt++)
                    mma8(acc[mt][nt], af[mt][0], af[mt][1], af[mt][2], af[mt][3],
                         bf[nt][0], bf[nt][1]);
        }
    }
}

// ---------------- GroupNorm ----------------------------------------------------
__global__ __launch_bounds__(512) void gn_kernel(const float* __restrict__ x,
                                                 const float* __restrict__ w,
                                                 const float* __restrict__ bv) {
    int bg = blockIdx.x;
    int b = bg >> 3, g = bg & 7;
    const float* xb = x + ((size_t)b * Cc + (size_t)g * CPG) * HWn;
    const int NEL = CPG * HWn;

    float s = 0.f, ss = 0.f;
    for (int i = threadIdx.x; i < NEL; i += blockDim.x) {
        float v = xb[i];
        s += v; ss += v * v;
    }
    __shared__ float rs[32], rss[32];
    #pragma unroll
    for (int o = 16; o; o >>= 1) {
        s  += __shfl_down_sync(0xffffffffu, s, o);
        ss += __shfl_down_sync(0xffffffffu, ss, o);
    }
    int lane = threadIdx.x & 31, wid = threadIdx.x >> 5;
    if (lane == 0) { rs[wid] = s; rss[wid] = ss; }
    __syncthreads();
    if (wid == 0) {
        s  = (lane < 16) ? rs[lane]  : 0.f;
        ss = (lane < 16) ? rss[lane] : 0.f;
        #pragma unroll
        for (int o = 16; o; o >>= 1) {
            s  += __shfl_down_sync(0xffffffffu, s, o);
            ss += __shfl_down_sync(0xffffffffu, ss, o);
        }
        if (lane == 0) { rs[0] = s; rss[0] = ss; }
    }
    __syncthreads();
    float mean = rs[0] / (float)NEL;
    float var  = rss[0] / (float)NEL - mean * mean;
    float rstd = rsqrtf(var + 1e-5f);

    float* out = g_xn + (size_t)b * HWn * Cc + (size_t)g * CPG;
    for (int i = threadIdx.x; i < NEL; i += blockDim.x) {
        int c = i & 31;
        int p = i >> 5;
        float v = xb[(size_t)c * HWn + p];
        out[(size_t)p * Cc + c] = (v - mean) * rstd * w[g * CPG + c] + bv[g * CPG + c];
    }
}

// ---------------- QKV GEMM (tf32): [4096 x 768] = xn[4096x256] * W^T ------------
__global__ __launch_bounds__(256) void qkv_kernel(const float* __restrict__ W,
                                                  const float* __restrict__ bias) {
    __shared__ float As[128 * PA];
    __shared__ float Bs[128 * PA];
    int b = blockIdx.z;
    int pm = blockIdx.y * 128;
    int on = blockIdx.x * 128;
    const float* Ag = g_xn + (size_t)b * HWn * Cc + (size_t)pm * Cc;
    const float* Bg = W + (size_t)on * Cc;

    float acc[2][8][4] = {};
    gemm_nt(Ag, Bg, Cc, Cc, Cc, As, Bs, acc);

    int t = threadIdx.x, wid = t >> 5, lane = t & 31, g = lane >> 2, t4 = lane & 3;
    int wm = (wid >> 1) * 32, wn = (wid & 1) * 64;
    float* dst = (on < 256) ? g_q : (on < 512) ? g_k : g_v;
    int obase = on & 255;
    dst += (size_t)b * HWn * Cc;

    #pragma unroll
    for (int nt = 0; nt < 8; nt++) {
        int ocol = wn + nt * 8 + t4 * 2;
        float2 bb = *(const float2*)&bias[on + ocol];
        #pragma unroll
        for (int mt = 0; mt < 2; mt++) {
            int p0 = pm + wm + mt * 16 + g;
            float2 v0 = { acc[mt][nt][0] + bb.x, acc[mt][nt][1] + bb.y };
            float2 v1 = { acc[mt][nt][2] + bb.x, acc[mt][nt][3] + bb.y };
            *(float2*)&dst[(size_t)p0 * Cc + obase + ocol]       = v0;
            *(float2*)&dst[(size_t)(p0 + 8) * Cc + obase + ocol] = v1;
        }
    }
}

// ---------------- scores GEMM (tf32): S[n][m] = q[n]·k[m] / 16 ------------------
__global__ __launch_bounds__(256) void scores_kernel() {
    __shared__ float As[128 * PA];
    __shared__ float Bs[128 * PA];
    int b = blockIdx.z;
    int nm = blockIdx.y * 128;
    int mn = blockIdx.x * 128;
    const float* Ag = g_q + (size_t)b * HWn * Cc + (size_t)nm * Cc;
    const float* Bg = g_k + (size_t)b * HWn * Cc + (size_t)mn * Cc;

    float acc[2][8][4] = {};
    gemm_nt(Ag, Bg, Cc, Cc, Cc, As, Bs, acc);

    int t = threadIdx.x, wid = t >> 5, lane = t & 31, g = lane >> 2, t4 = lane & 3;
    int wm = (wid >> 1) * 32, wn = (wid & 1) * 64;
    const float scale = 0.0625f;
    float* S = g_sc + (size_t)b * HWn * HWn;

    #pragma unroll
    for (int mt = 0; mt < 2; mt++) {
        int n0 = nm + wm + mt * 16 + g;
        #pragma unroll
        for (int nt = 0; nt < 8; nt++) {
            int m0 = mn + wn + nt * 8 + t4 * 2;
            float2 v0 = { acc[mt][nt][0] * scale, acc[mt][nt][1] * scale };
            float2 v1 = { acc[mt][nt][2] * scale, acc[mt][nt][3] * scale };
            *(float2*)&S[(size_t)n0 * HWn + m0]       = v0;
            *(float2*)&S[(size_t)(n0 + 8) * HWn + m0] = v1;
        }
    }
}

// ---------------- row softmax over m (4096) --------------------------------------
__global__ __launch_bounds__(256) void softmax_kernel() {
    size_t row = blockIdx.x;
    float* S = g_sc + row * HWn;
    float v[16];
    float mx = -1e30f;
    #pragma unroll
    for (int i = 0; i < 16; i++) {
        v[i] = S[threadIdx.x + 256 * i];
        mx = fmaxf(mx, v[i]);
    }
    __shared__ float redm[8], reds[8];
    int lane = threadIdx.x & 31, wid = threadIdx.x >> 5;
    #pragma unroll
    for (int o = 16; o; o >>= 1) mx = fmaxf(mx, __shfl_xor_sync(0xffffffffu, mx, o));
    if (lane == 0) redm[wid] = mx;
    __syncthreads();
    mx = redm[0];
    #pragma unroll
    for (int i = 1; i < 8; i++) mx = fmaxf(mx, redm[i]);

    float sum = 0.f;
    #pragma unroll
    for (int i = 0; i < 16; i++) {
        v[i] = __expf(v[i] - mx);
        sum += v[i];
    }
    #pragma unroll
    for (int o = 16; o; o >>= 1) sum += __shfl_xor_sync(0xffffffffu, sum, o);
    if (lane == 0) reds[wid] = sum;
    __syncthreads();
    sum = reds[0];
    #pragma unroll
    for (int i = 1; i < 8; i++) sum += reds[i];

    float inv = 1.0f / sum;
    #pragma unroll
    for (int i = 0; i < 16; i++)
        S[threadIdx.x + 256 * i] = v[i] * inv;
}

// ---------------- PV GEMM (tf32): ao[n][c] = sum_m attn[n][m] v[m][c] -----------
__global__ __launch_bounds__(256) void pv_kernel() {
    __shared__ float As[128 * PA];
    __shared__ float Vs[16 * PVP];
    int b = blockIdx.z;
    int nm = blockIdx.y * 128;  // token tile
    int cn = blockIdx.x * 128;  // channel tile
    const float* Ag = g_sc + (size_t)b * HWn * HWn + (size_t)nm * HWn;
    const float* Vg = g_v + (size_t)b * HWn * Cc;

    int t = threadIdx.x;
    int r = t >> 1, cc = (t & 1) * 8;
    int rv = t >> 5, cv = (t & 31) * 4;
    int wid = t >> 5, lane = t & 31, g = lane >> 2, t4 = lane & 3;
    int wm = (wid >> 1) * 32, wn = (wid & 1) * 64;

    float acc[2][8][4] = {};

    #pragma unroll 1
    for (int kb = 0; kb < HWn; kb += 16) {
        float4 av0 = *(const float4*)(Ag + (size_t)r * HWn + kb + cc);
        float4 av1 = *(const float4*)(Ag + (size_t)r * HWn + kb + cc + 4);
        float4 vv0 = *(const float4*)(Vg + (size_t)(kb + rv) * Cc + cn + cv);
        float4 vv1 = *(const float4*)(Vg + (size_t)(kb + rv + 8) * Cc + cn + cv);
        __syncthreads();
        *(float4*)&As[r * PA + cc]       = tf32r4(av0);
        *(float4*)&As[r * PA + cc + 4]   = tf32r4(av1);
        *(float4*)&Vs[rv * PVP + cv]       = tf32r4(vv0);
        *(float4*)&Vs[(rv + 8) * PVP + cv] = tf32r4(vv1);
        __syncthreads();
        #pragma unroll
        for (int ks = 0; ks < 16; ks += 8) {
            uint32_t af[2][4];
            #pragma unroll
            for (int mt = 0; mt < 2; mt++) {
                int row = (wm + mt * 16 + g) * PA + ks + t4;
                af[mt][0] = U(As[row]);
                af[mt][1] = U(As[row + 8 * PA]);
                af[mt][2] = U(As[row + 4]);
                af[mt][3] = U(As[row + 8 * PA + 4]);
            }
            uint32_t bf[8][2];
            #pragma unroll
            for (int nt = 0; nt < 8; nt++) {
                int col = wn + nt * 8 + g;
                bf[nt][0] = U(Vs[(ks + t4) * PVP + col]);
                bf[nt][1] = U(Vs[(ks + t4 + 4) * PVP + col]);
            }
            #pragma unroll
            for (int mt = 0; mt < 2; mt++)
                #pragma unroll
                for (int nt = 0; nt < 8; nt++)
                    mma8(acc[mt][nt], af[mt][0], af[mt][1], af[mt][2], af[mt][3],
                         bf[nt][0], bf[nt][1]);
        }
    }

    float* AO = g_ao + (size_t)b * HWn * Cc;
    #pragma unroll
    for (int mt = 0; mt < 2; mt++) {
        int p0 = nm + wm + mt * 16 + g;
        #pragma unroll
        for (int nt = 0; nt < 8; nt++) {
            int c0 = cn + wn + nt * 8 + t4 * 2;
            float2 v0 = { acc[mt][nt][0], acc[mt][nt][1] };
            float2 v1 = { acc[mt][nt][2], acc[mt][nt][3] };
            *(float2*)&AO[(size_t)p0 * Cc + c0]       = v0;
            *(float2*)&AO[(size_t)(p0 + 8) * Cc + c0] = v1;
        }
    }
}

// ---------------- proj GEMM (tf32) + residual: out[o][p] ------------------------
__global__ __launch_bounds__(256) void proj_kernel(const float* __restrict__ x,
                                                   const float* __restrict__ W,
                                                   const float* __restrict__ pb,
                                                   float* __restrict__ out) {
    __shared__ float As[128 * PA];
    __shared__ float Bs[128 * PA];
    int b = blockIdx.z;
    int om = blockIdx.y * 128;  // output-channel tile
    int pn = blockIdx.x * 128;  // token tile
    const float* Ag = W + (size_t)om * Cc;
    const float* Bg = g_ao + (size_t)b * HWn * Cc + (size_t)pn * Cc;

    float acc[2][8][4] = {};
    gemm_nt(Ag, Bg, Cc, Cc, Cc, As, Bs, acc);

    int t = threadIdx.x, wid = t >> 5, lane = t & 31, g = lane >> 2, t4 = lane & 3;
    int wm = (wid >> 1) * 32, wn = (wid & 1) * 64;

    #pragma unroll
    for (int mt = 0; mt < 2; mt++) {
        int o0 = om + wm + mt * 16 + g;
        float b0 = pb[o0], b1 = pb[o0 + 8];
        #pragma unroll
        for (int nt = 0; nt < 8; nt++) {
            int p0 = pn + wn + nt * 8 + t4 * 2;
            size_t off0 = ((size_t)b * Cc + o0) * HWn + p0;
            size_t off1 = ((size_t)b * Cc + o0 + 8) * HWn + p0;
            float2 x0 = *(const float2*)&x[off0];
            float2 x1 = *(const float2*)&x[off1];
            float2 v0 = { acc[mt][nt][0] + b0 + x0.x, acc[mt][nt][1] + b0 + x0.y };
            float2 v1 = { acc[mt][nt][2] + b1 + x1.x, acc[mt][nt][3] + b1 + x1.y };
            *(float2*)&out[off0] = v0;
            *(float2*)&out[off1] = v1;
        }
    }
}

// ---------------- launch ---------------------------------------------------------
extern "C" void kernel_launch(void* const* d_in, const int* in_sizes, int n_in,
                              void* d_out, int out_size) {
    const float* x  = (const float*)d_in[0];
    const float* nw = (const float*)d_in[1];
    const float* nb = (const float*)d_in[2];
    const float* qw = (const float*)d_in[3];
    const float* qb = (const float*)d_in[4];
    const float* pw = (const float*)d_in[5];
    const float* pb = (const float*)d_in[6];
    float* out = (float*)d_out;

    gn_kernel<<<Bn * 8, 512>>>(x, nw, nb);
    qkv_kernel<<<dim3(6, 32, 8), 256>>>(qw, qb);
    scores_kernel<<<dim3(32, 32, 8), 256>>>();
    softmax_kernel<<<Bn * HWn, 256>>>();
    pv_kernel<<<dim3(2, 32, 8), 256>>>();
    proj_kernel<<<dim3(32, 2, 8), 256>>>(x, pw, pb, out);
}

// round 3
// speedup vs baseline: 3.2414x; 1.1871x over previous
#include <cuda_runtime.h>
#include <cstdint>

#define Bn   8
#define Cc   256
#define HWn  4096
#define CPG  32
#define PA   20    // smem pitch for qkv/proj [128 rows][16 k] tiles

// flash smem pitches (floats)
#define QP 260
#define KP 68
#define VP 264
#define PP 68
// flash smem layout (float offsets)
#define OFF_Q   0
#define OFF_K   (OFF_Q + 64*QP)          // Qs: 64 x 260
#define OFF_V   (OFF_K + 2*64*KP)        // Ks: 2 bufs x 64 x 68
#define OFF_P   (OFF_V + 2*32*VP)        // Vs: 2 bufs x 32 x 264
#define OFF_RM  (OFF_P + 64*PP)          // Ps: 64 x 68
#define OFF_RS  (OFF_RM + 128)
#define SMEM_FLOATS (OFF_RS + 128)
#define SMEM_BYTES  (SMEM_FLOATS * 4)    // 187,392 B

// ---------------- scratch -----------------------------------------------------
__device__ float g_xn[(size_t)Bn * HWn * Cc];
__device__ float g_q [(size_t)Bn * HWn * Cc];
__device__ float g_k [(size_t)Bn * HWn * Cc];
__device__ float g_v [(size_t)Bn * HWn * Cc];
__device__ float g_ao[(size_t)Bn * HWn * Cc];

// ---------------- helpers ------------------------------------------------------
__device__ __forceinline__ float tf32r(float x) {
    uint32_t r;
    asm("cvt.rna.tf32.f32 %0, %1;" : "=r"(r) : "f"(x));
    return __uint_as_float(r);
}
__device__ __forceinline__ float4 tf32r4(float4 v) {
    float4 o; o.x = tf32r(v.x); o.y = tf32r(v.y); o.z = tf32r(v.z); o.w = tf32r(v.w);
    return o;
}
__device__ __forceinline__ void mma8(float c[4], uint32_t a0, uint32_t a1, uint32_t a2,
                                     uint32_t a3, uint32_t b0, uint32_t b1) {
    asm("mma.sync.aligned.m16n8k8.row.col.f32.tf32.tf32.f32 "
        "{%0,%1,%2,%3},{%4,%5,%6,%7},{%8,%9},{%0,%1,%2,%3};"
        : "+f"(c[0]), "+f"(c[1]), "+f"(c[2]), "+f"(c[3])
        : "r"(a0), "r"(a1), "r"(a2), "r"(a3), "r"(b0), "r"(b1));
}
#define U(x) __float_as_uint(x)

__device__ __forceinline__ void cp16(float* dst, const float* src) {
    uint32_t d = (uint32_t)__cvta_generic_to_shared(dst);
    asm volatile("cp.async.cg.shared.global [%0], [%1], 16;\n" :: "r"(d), "l"(src));
}
__device__ __forceinline__ void cpcommit() { asm volatile("cp.async.commit_group;\n"); }
template<int N> __device__ __forceinline__ void cpwait() {
    asm volatile("cp.async.wait_group %0;\n" :: "n"(N));
}

// ---------------- GroupNorm ----------------------------------------------------
__global__ __launch_bounds__(512) void gn_kernel(const float* __restrict__ x,
                                                 const float* __restrict__ w,
                                                 const float* __restrict__ bv) {
    int bg = blockIdx.x;
    int b = bg >> 3, g = bg & 7;
    const float* xb = x + ((size_t)b * Cc + (size_t)g * CPG) * HWn;
    const int NEL = CPG * HWn;

    float s = 0.f, ss = 0.f;
    for (int i = threadIdx.x; i < NEL; i += blockDim.x) {
        float v = xb[i];
        s += v; ss += v * v;
    }
    __shared__ float rs[32], rss[32];
    #pragma unroll
    for (int o = 16; o; o >>= 1) {
        s  += __shfl_down_sync(0xffffffffu, s, o);
        ss += __shfl_down_sync(0xffffffffu, ss, o);
    }
    int lane = threadIdx.x & 31, wid = threadIdx.x >> 5;
    if (lane == 0) { rs[wid] = s; rss[wid] = ss; }
    __syncthreads();
    if (wid == 0) {
        s  = (lane < 16) ? rs[lane]  : 0.f;
        ss = (lane < 16) ? rss[lane] : 0.f;
        #pragma unroll
        for (int o = 16; o; o >>= 1) {
            s  += __shfl_down_sync(0xffffffffu, s, o);
            ss += __shfl_down_sync(0xffffffffu, ss, o);
        }
        if (lane == 0) { rs[0] = s; rss[0] = ss; }
    }
    __syncthreads();
    float mean = rs[0] / (float)NEL;
    float var  = rss[0] / (float)NEL - mean * mean;
    float rstd = rsqrtf(var + 1e-5f);

    float* out = g_xn + (size_t)b * HWn * Cc + (size_t)g * CPG;
    for (int i = threadIdx.x; i < NEL; i += blockDim.x) {
        int c = i & 31;
        int p = i >> 5;
        float v = xb[(size_t)c * HWn + p];
        out[(size_t)p * Cc + c] = (v - mean) * rstd * w[g * CPG + c] + bv[g * CPG + c];
    }
}

// ---------------- shared NT GEMM mainloop (qkv / proj) --------------------------
__device__ __forceinline__ void gemm_nt(const float* __restrict__ Ag,
                                        const float* __restrict__ Bg,
                                        int K, int lda, int ldb,
                                        float* As, float* Bs,
                                        float acc[2][8][4]) {
    int t = threadIdx.x;
    int r = t >> 1, cc = (t & 1) * 8;
    int wid = t >> 5, lane = t & 31, g = lane >> 2, t4 = lane & 3;
    int wm = (wid >> 1) * 32, wn = (wid & 1) * 64;

    #pragma unroll 1
    for (int kb = 0; kb < K; kb += 16) {
        float4 av0 = *(const float4*)(Ag + (size_t)r * lda + kb + cc);
        float4 av1 = *(const float4*)(Ag + (size_t)r * lda + kb + cc + 4);
        float4 bv0 = *(const float4*)(Bg + (size_t)r * ldb + kb + cc);
        float4 bv1 = *(const float4*)(Bg + (size_t)r * ldb + kb + cc + 4);
        __syncthreads();
        *(float4*)&As[r * PA + cc]     = tf32r4(av0);
        *(float4*)&As[r * PA + cc + 4] = tf32r4(av1);
        *(float4*)&Bs[r * PA + cc]     = tf32r4(bv0);
        *(float4*)&Bs[r * PA + cc + 4] = tf32r4(bv1);
        __syncthreads();
        #pragma unroll
        for (int ks = 0; ks < 16; ks += 8) {
            uint32_t af[2][4];
            #pragma unroll
            for (int mt = 0; mt < 2; mt++) {
                int row = (wm + mt * 16 + g) * PA + ks + t4;
                af[mt][0] = U(As[row]);
                af[mt][1] = U(As[row + 8 * PA]);
                af[mt][2] = U(As[row + 4]);
                af[mt][3] = U(As[row + 8 * PA + 4]);
            }
            uint32_t bf[8][2];
            #pragma unroll
            for (int nt = 0; nt < 8; nt++) {
                int row = (wn + nt * 8 + g) * PA + ks + t4;
                bf[nt][0] = U(Bs[row]);
                bf[nt][1] = U(Bs[row + 4]);
            }
            #pragma unroll
            for (int mt = 0; mt < 2; mt++)
                #pragma unroll
                for (int nt = 0; nt < 8; nt++)
                    mma8(acc[mt][nt], af[mt][0], af[mt][1], af[mt][2], af[mt][3],
                         bf[nt][0], bf[nt][1]);
        }
    }
}

// ---------------- QKV GEMM -------------------------------------------------------
__global__ __launch_bounds__(256) void qkv_kernel(const float* __restrict__ W,
                                                  const float* __restrict__ bias) {
    __shared__ float As[128 * PA];
    __shared__ float Bs[128 * PA];
    int b = blockIdx.z;
    int pm = blockIdx.y * 128;
    int on = blockIdx.x * 128;
    const float* Ag = g_xn + (size_t)b * HWn * Cc + (size_t)pm * Cc;
    const float* Bg = W + (size_t)on * Cc;

    float acc[2][8][4] = {};
    gemm_nt(Ag, Bg, Cc, Cc, Cc, As, Bs, acc);

    int t = threadIdx.x, wid = t >> 5, lane = t & 31, g = lane >> 2, t4 = lane & 3;
    int wm = (wid >> 1) * 32, wn = (wid & 1) * 64;
    float* dst = (on < 256) ? g_q : (on < 512) ? g_k : g_v;
    int obase = on & 255;
    dst += (size_t)b * HWn * Cc;

    #pragma unroll
    for (int nt = 0; nt < 8; nt++) {
        int ocol = wn + nt * 8 + t4 * 2;
        float2 bb = *(const float2*)&bias[on + ocol];
        #pragma unroll
        for (int mt = 0; mt < 2; mt++) {
            int p0 = pm + wm + mt * 16 + g;
            float2 v0 = { acc[mt][nt][0] + bb.x, acc[mt][nt][1] + bb.y };
            float2 v1 = { acc[mt][nt][2] + bb.x, acc[mt][nt][3] + bb.y };
            *(float2*)&dst[(size_t)p0 * Cc + obase + ocol]       = v0;
            *(float2*)&dst[(size_t)(p0 + 8) * Cc + obase + ocol] = v1;
        }
    }
}

// ---------------- flash attention: scores + softmax + PV fused ------------------
__device__ __forceinline__ void copyK(const float* Kg, int kt, int kc, float* kb, int t) {
    const float* src = Kg + (size_t)(kt * 64) * Cc + kc * 64;
    #pragma unroll
    for (int i = 0; i < 4; i++) {
        int idx = t + 256 * i;
        int row = idx >> 4, c4 = (idx & 15) * 4;
        cp16(kb + row * KP + c4, src + (size_t)row * Cc + c4);
    }
}
__device__ __forceinline__ void copyV(const float* Vg, int kt, int half, float* vb, int t) {
    const float* src = Vg + (size_t)(kt * 64 + half * 32) * Cc;
    #pragma unroll
    for (int i = 0; i < 8; i++) {
        int idx = t + 256 * i;
        int row = idx >> 6, c4 = (idx & 63) * 4;
        cp16(vb + row * VP + c4, src + (size_t)row * Cc + c4);
    }
}
__device__ __forceinline__ void mmaS(const float* Qs, const float* kb, float sacc[4][4],
                                     int kc, int wm, int ni, int g, int t4) {
    #pragma unroll
    for (int ks = 0; ks < 64; ks += 8) {
        int kq = kc * 64 + ks;
        uint32_t a0 = U(Qs[(wm + g) * QP + kq + t4]);
        uint32_t a1 = U(Qs[(wm + g + 8) * QP + kq + t4]);
        uint32_t a2 = U(Qs[(wm + g) * QP + kq + t4 + 4]);
        uint32_t a3 = U(Qs[(wm + g + 8) * QP + kq + t4 + 4]);
        #pragma unroll
        for (int nt = 0; nt < 4; nt++) {
            int r = ni * 32 + nt * 8 + g;
            uint32_t b0 = U(kb[r * KP + ks + t4]);
            uint32_t b1 = U(kb[r * KP + ks + t4 + 4]);
            mma8(sacc[nt], a0, a1, a2, a3, b0, b1);
        }
    }
}

__global__ void __launch_bounds__(256, 1) flash_kernel() {
    extern __shared__ float sm[];
    float* Qs = sm + OFF_Q;
    float* Kb0 = sm + OFF_K;
    float* Kb1 = sm + OFF_K + 64 * KP;
    float* Vb0 = sm + OFF_V;
    float* Vb1 = sm + OFF_V + 32 * VP;
    float* Ps = sm + OFF_P;
    float* RM = sm + OFF_RM;   // [2][64]
    float* RS = sm + OFF_RS;   // [2][64]

    int b = blockIdx.y;
    int qbase = blockIdx.x * 64;
    size_t bo = (size_t)b * HWn * Cc;
    const float* Qg = g_q + bo + (size_t)qbase * Cc;
    const float* Kg = g_k + bo;
    const float* Vg = g_v + bo;

    int t = threadIdx.x;
    int wid = t >> 5, lane = t & 31, g = lane >> 2, t4 = lane & 3;
    int mi = wid >> 1, ni = wid & 1;
    int wm = mi * 16;

    float oacc[16][4] = {};
    float M0 = -1e30f, M1 = -1e30f, L0 = 0.f, L1 = 0.f;

    // prologue: first K chunk in flight  (pending = 1 at each kt-loop entry)
    copyK(Kg, 0, 0, Kb0, t); cpcommit();

    // Q tile: load + tf32 round into smem (consumed after first syncthreads)
    #pragma unroll
    for (int i = 0; i < 16; i++) {
        int idx = t + 256 * i;
        int row = idx >> 6, c4 = (idx & 63) * 4;
        float4 v = *(const float4*)(Qg + (size_t)row * Cc + c4);
        *(float4*)&Qs[row * QP + c4] = tf32r4(v);
    }

    for (int kt = 0; kt < 64; kt++) {
        copyV(Vg, kt, 0, Vb0, t); cpcommit();   // pending 2
        copyK(Kg, kt, 1, Kb1, t); cpcommit();   // pending 3
        copyV(Vg, kt, 1, Vb1, t); cpcommit();   // pending 4

        float sacc[4][4] = {};
        cpwait<3>(); __syncthreads();           // KC0 ready
        mmaS(Qs, Kb0, sacc, 0, wm, ni, g, t4);
        __syncthreads();
        copyK(Kg, kt, 2, Kb0, t); cpcommit();   // pending 4
        cpwait<2>(); __syncthreads();           // VC0, KC1 ready
        mmaS(Qs, Kb1, sacc, 1, wm, ni, g, t4);
        __syncthreads();
        copyK(Kg, kt, 3, Kb1, t); cpcommit();   // pending 3
        cpwait<1>(); __syncthreads();           // VC1, KC2 ready
        mmaS(Qs, Kb0, sacc, 2, wm, ni, g, t4);
        __syncthreads();
        if (kt < 63) { copyK(Kg, kt + 1, 0, Kb0, t); cpcommit(); }  // pending 2
        if (kt < 63) { cpwait<1>(); } else { cpwait<0>(); }         // KC3 ready
        __syncthreads();
        mmaS(Qs, Kb1, sacc, 3, wm, ni, g, t4);

        // ---- online softmax (log2 domain; scale = log2(e)/sqrt(256)) ----
        const float SCL = 0.090169311f;
        float mx0 = -1e30f, mx1 = -1e30f;
        #pragma unroll
        for (int nt = 0; nt < 4; nt++) {
            #pragma unroll
            for (int j = 0; j < 4; j++) sacc[nt][j] *= SCL;
            mx0 = fmaxf(mx0, fmaxf(sacc[nt][0], sacc[nt][1]));
            mx1 = fmaxf(mx1, fmaxf(sacc[nt][2], sacc[nt][3]));
        }
        mx0 = fmaxf(mx0, __shfl_xor_sync(0xffffffffu, mx0, 1));
        mx0 = fmaxf(mx0, __shfl_xor_sync(0xffffffffu, mx0, 2));
        mx1 = fmaxf(mx1, __shfl_xor_sync(0xffffffffu, mx1, 1));
        mx1 = fmaxf(mx1, __shfl_xor_sync(0xffffffffu, mx1, 2));
        if (t4 == 0) { RM[ni * 64 + wm + g] = mx0; RM[ni * 64 + wm + g + 8] = mx1; }
        __syncthreads();
        float tm0 = fmaxf(RM[wm + g],     RM[64 + wm + g]);
        float tm1 = fmaxf(RM[wm + g + 8], RM[64 + wm + g + 8]);
        float Mn0 = fmaxf(M0, tm0), Mn1 = fmaxf(M1, tm1);
        float f0 = exp2f(M0 - Mn0), f1 = exp2f(M1 - Mn1);
        M0 = Mn0; M1 = Mn1;
        float s0 = 0.f, s1 = 0.f;
        #pragma unroll
        for (int nt = 0; nt < 4; nt++) {
            float p00 = exp2f(sacc[nt][0] - Mn0);
            float p01 = exp2f(sacc[nt][1] - Mn0);
            float p10 = exp2f(sacc[nt][2] - Mn1);
            float p11 = exp2f(sacc[nt][3] - Mn1);
            s0 += p00 + p01; s1 += p10 + p11;
            int c = ni * 32 + nt * 8 + t4 * 2;
            float2 u0 = { tf32r(p00), tf32r(p01) };
            float2 u1 = { tf32r(p10), tf32r(p11) };
            *(float2*)&Ps[(wm + g) * PP + c]     = u0;
            *(float2*)&Ps[(wm + g + 8) * PP + c] = u1;
        }
        s0 += __shfl_xor_sync(0xffffffffu, s0, 1);
        s0 += __shfl_xor_sync(0xffffffffu, s0, 2);
        s1 += __shfl_xor_sync(0xffffffffu, s1, 1);
        s1 += __shfl_xor_sync(0xffffffffu, s1, 2);
        if (t4 == 0) { RS[ni * 64 + wm + g] = s0; RS[ni * 64 + wm + g + 8] = s1; }
        __syncthreads();   // also publishes Ps
        L0 = L0 * f0 + RS[wm + g]     + RS[64 + wm + g];
        L1 = L1 * f1 + RS[wm + g + 8] + RS[64 + wm + g + 8];
        #pragma unroll
        for (int nt2 = 0; nt2 < 16; nt2++) {
            oacc[nt2][0] *= f0; oacc[nt2][1] *= f0;
            oacc[nt2][2] *= f1; oacc[nt2][3] *= f1;
        }

        // ---- PV: oacc += P[64x64] @ V[64x256] ----
        #pragma unroll
        for (int vb = 0; vb < 2; vb++) {
            const float* V = vb ? Vb1 : Vb0;
            #pragma unroll
            for (int m8 = 0; m8 < 32; m8 += 8) {
                int mp = vb * 32 + m8;
                uint32_t a0 = U(Ps[(wm + g) * PP + mp + t4]);
                uint32_t a1 = U(Ps[(wm + g + 8) * PP + mp + t4]);
                uint32_t a2 = U(Ps[(wm + g) * PP + mp + t4 + 4]);
                uint32_t a3 = U(Ps[(wm + g + 8) * PP + mp + t4 + 4]);
                #pragma unroll
                for (int nt2 = 0; nt2 < 16; nt2++) {
                    int c = ni * 128 + nt2 * 8 + g;
                    uint32_t b0 = U(V[(m8 + t4) * VP + c]);
                    uint32_t b1 = U(V[(m8 + t4 + 4) * VP + c]);
                    mma8(oacc[nt2], a0, a1, a2, a3, b0, b1);
                }
            }
        }
        __syncthreads();  // done with Vb*, Ps, Kb1 before next kt refills
    }

    float r0 = 1.0f / L0, r1 = 1.0f / L1;
    float* AO = g_ao + bo;
    #pragma unroll
    for (int nt2 = 0; nt2 < 16; nt2++) {
        int c = ni * 128 + nt2 * 8 + t4 * 2;
        int row = qbase + wm + g;
        float2 v0 = { oacc[nt2][0] * r0, oacc[nt2][1] * r0 };
        float2 v1 = { oacc[nt2][2] * r1, oacc[nt2][3] * r1 };
        *(float2*)&AO[(size_t)row * Cc + c]       = v0;
        *(float2*)&AO[(size_t)(row + 8) * Cc + c] = v1;
    }
}

// ---------------- proj GEMM + residual -------------------------------------------
__global__ __launch_bounds__(256) void proj_kernel(const float* __restrict__ x,
                                                   const float* __restrict__ W,
                                                   const float* __restrict__ pb,
                                                   float* __restrict__ out) {
    __shared__ float As[128 * PA];
    __shared__ float Bs[128 * PA];
    int b = blockIdx.z;
    int om = blockIdx.y * 128;
    int pn = blockIdx.x * 128;
    const float* Ag = W + (size_t)om * Cc;
    const float* Bg = g_ao + (size_t)b * HWn * Cc + (size_t)pn * Cc;

    float acc[2][8][4] = {};
    gemm_nt(Ag, Bg, Cc, Cc, Cc, As, Bs, acc);

    int t = threadIdx.x, wid = t >> 5, lane = t & 31, g = lane >> 2, t4 = lane & 3;
    int wm = (wid >> 1) * 32, wn = (wid & 1) * 64;

    #pragma unroll
    for (int mt = 0; mt < 2; mt++) {
        int o0 = om + wm + mt * 16 + g;
        float b0 = pb[o0], b1 = pb[o0 + 8];
        #pragma unroll
        for (int nt = 0; nt < 8; nt++) {
            int p0 = pn + wn + nt * 8 + t4 * 2;
            size_t off0 = ((size_t)b * Cc + o0) * HWn + p0;
            size_t off1 = ((size_t)b * Cc + o0 + 8) * HWn + p0;
            float2 x0 = *(const float2*)&x[off0];
            float2 x1 = *(const float2*)&x[off1];
            float2 v0 = { acc[mt][nt][0] + b0 + x0.x, acc[mt][nt][1] + b0 + x0.y };
            float2 v1 = { acc[mt][nt][2] + b1 + x1.x, acc[mt][nt][3] + b1 + x1.y };
            *(float2*)&out[off0] = v0;
            *(float2*)&out[off1] = v1;
        }
    }
}

// ---------------- launch ---------------------------------------------------------
extern "C" void kernel_launch(void* const* d_in, const int* in_sizes, int n_in,
                              void* d_out, int out_size) {
    const float* x  = (const float*)d_in[0];
    const float* nw = (const float*)d_in[1];
    const float* nb = (const float*)d_in[2];
    const float* qw = (const float*)d_in[3];
    const float* qb = (const float*)d_in[4];
    const float* pw = (const float*)d_in[5];
    const float* pb = (const float*)d_in[6];
    float* out = (float*)d_out;

    cudaFuncSetAttribute(flash_kernel, cudaFuncAttributeMaxDynamicSharedMemorySize,
                         SMEM_BYTES);

    gn_kernel<<<Bn * 8, 512>>>(x, nw, nb);
    qkv_kernel<<<dim3(6, 32, 8), 256>>>(qw, qb);
    flash_kernel<<<dim3(64, 8), 256, SMEM_BYTES>>>();
    proj_kernel<<<dim3(32, 2, 8), 256>>>(x, pw, pb, out);
}